// round 14
// baseline (speedup 1.0000x reference)
#include <cuda_runtime.h>
#include <math.h>

#if defined(__CUDA_ARCH_FEAT_SM103_ALL) || defined(__CUDA_ARCH_FEAT_SM100_ALL) || defined(__CUDA_ARCH_SPECIFIC__)
#define F32X2_OK 1
#else
#define F32X2_OK 0
#endif

#define BB 256
#define TT 512
#define II 256
#define HH 512
#define AA 18
#define KK 768
#define NS 4            // k slices of the recurrence (K = 512)
#define KS 128          // k per slice
#define JT 128          // cols per CTA (step)
#define RT 16           // rows per CTA (step)

// ---------------- scratch (static device globals; no allocation) ----------------
__device__ float g_W[(size_t)KK * HH];             // [k][j] k<512 -> W_hh[j][k], else W_ih[j][k-512]
__device__ float g_bias[HH];
__device__ float g_part[2][NS][BB][HH];            // per-slice recurrence partials (parity buffered)
__device__ float g_proj[BB][TT][HH];               // x-projection + bias, sorted-row index (268MB)
__device__ float g_hout[(size_t)BB * TT * HH];
__device__ int   g_perm[BB];
__device__ int   g_active[TT];

// ---------------- cp.async ----------------
__device__ __forceinline__ void cpa16(void* sdst, const void* gsrc) {
    unsigned s = (unsigned)__cvta_generic_to_shared(sdst);
    asm volatile("cp.async.cg.shared.global [%0], [%1], 16;\n" :: "r"(s), "l"(gsrc));
}
#define CPA_COMMIT() asm volatile("cp.async.commit_group;\n" ::: "memory")
#define CPA_WAIT0()  asm volatile("cp.async.wait_group 0;\n" ::: "memory")

// ---------------- f32x2 packed FMA (sm_103a pass only) ----------------
#if F32X2_OK
__device__ __forceinline__ void fma2(unsigned long long& d, unsigned long long a, unsigned long long b) {
    asm("fma.rn.f32x2 %0, %1, %2, %0;" : "+l"(d) : "l"(a), "l"(b));
}
__device__ __forceinline__ unsigned long long packdup(float h) {
    unsigned long long r;
    unsigned hb = __float_as_uint(h);
    asm("mov.b64 %0, {%1, %1};" : "=l"(r) : "r"(hb));
    return r;
}
__device__ __forceinline__ void unpack2(unsigned long long v, float& lo, float& hi) {
    unsigned a, b;
    asm("mov.b64 {%0, %1}, %2;" : "=r"(a), "=r"(b) : "l"(v));
    lo = __uint_as_float(a); hi = __uint_as_float(b);
}
#endif

// ---------------- prep: counting sort by length (desc) + active counts ----------------
__global__ void prep_sort(const int* __restrict__ lengths) {
    __shared__ int s_len[BB];
    __shared__ int s_hist[TT + 1];
    __shared__ int s_S[TT + 1];
    __shared__ int s_base[TT + 1];
    int tid = threadIdx.x;          // 512 threads
    if (tid < BB) s_len[tid] = lengths[tid];
    for (int i = tid; i <= TT; i += blockDim.x) s_hist[i] = 0;
    __syncthreads();
    if (tid < BB) atomicAdd(&s_hist[s_len[tid]], 1);
    __syncthreads();
    if (tid == 0) {
        s_S[TT] = 0;
        for (int v = TT - 1; v >= 0; --v) s_S[v] = s_S[v + 1] + s_hist[v + 1];
    }
    __syncthreads();
    for (int i = tid; i <= TT; i += blockDim.x) s_base[i] = s_S[i];
    if (tid < TT) g_active[tid] = s_S[tid];
    __syncthreads();
    if (tid < BB) {
        int pos = atomicAdd(&s_base[s_len[tid]], 1);
        g_perm[pos] = tid;
    }
}

// ---------------- prep: pack W concat k-major, bias ----------------
__global__ void prep_pack(const float* __restrict__ W_ih, const float* __restrict__ W_hh,
                          const float* __restrict__ b_ih, const float* __restrict__ b_hh) {
    int idx = blockIdx.x * blockDim.x + threadIdx.x;
    int stride = gridDim.x * blockDim.x;
    for (int i = idx; i < KK * HH; i += stride) {
        int k = i / HH, j = i % HH;
        g_W[i] = (k < HH) ? W_hh[(size_t)j * HH + k] : W_ih[(size_t)j * II + (k - HH)];
    }
    for (int i = idx; i < HH; i += stride) g_bias[i] = b_ih[i] + b_hh[i];
}

// ---------------- proj kernel: proj[r][t][:] = x[perm[r]][t] @ W_ih^T + bias ----------------
// grid (4 cg of 128 cols, 4 rg of 64 rows, 512 t), 512 threads, smem 192KB (s_x 64K | s_w 128K).
// Gated: CTA exits if its row block is entirely past active[t].
__global__ __launch_bounds__(512, 1) void proj_kernel(const float* __restrict__ x) {
    int t  = blockIdx.z;
    int a  = g_active[t];
    int r0 = blockIdx.y * 64;
    if (r0 >= a) return;
    int j0 = blockIdx.x * JT;
    int tid = threadIdx.x;

    extern __shared__ char smem_raw[];
    float (*s_x)[II] = (float (*)[II])smem_raw;                  // 64 x 256 = 64 KB
    float (*s_w)[JT] = (float (*)[JT])(smem_raw + 64 * II * 4);  // 256 x 128 = 128 KB
    __shared__ int s_b[64];

    if (tid < 64) s_b[tid] = g_perm[r0 + tid];

    // W_ih slice (k-major rows 512..767 of g_W) -> smem
    {
        const float* gw = g_W + (size_t)HH * HH + j0;   // k = 512 + i
        #pragma unroll
        for (int q = 0; q < 16; ++q) {
            int p  = tid + q * 512;
            int kk = p >> 5;
            int jj = (p & 31) * 4;
            cpa16(&s_w[kk][jj], gw + (size_t)kk * HH + jj);
        }
        CPA_COMMIT();
    }
    __syncthreads();   // s_b visible

    // stage x rows (4096 float4, 8/thread)
    #pragma unroll
    for (int q = 0; q < 8; ++q) {
        int p  = tid + q * 512;
        int rl = p >> 6;
        int il = (p & 63) * 4;
        *(float4*)&s_x[rl][il] =
            *(const float4*)&x[((size_t)s_b[rl] * TT + t) * II + il];
    }
    CPA_WAIT0();
    __syncthreads();

    // GEMM 64x128, per-thread 4 rows x 4 cols, K = 256
    int ty = tid >> 5;          // 0..15
    int tx = tid & 31;          // 0..31
    int cb = tx * 4;

#if F32X2_OK
    unsigned long long acc2[4][2];
    #pragma unroll
    for (int i = 0; i < 4; ++i) { acc2[i][0] = 0ull; acc2[i][1] = 0ull; }
#else
    float acc[4][4];
    #pragma unroll
    for (int i = 0; i < 4; ++i)
        #pragma unroll
        for (int jj = 0; jj < 4; ++jj) acc[i][jj] = 0.f;
#endif

    #pragma unroll 4
    for (int k4 = 0; k4 < II / 4; ++k4) {
        float4 hv[4];
        #pragma unroll
        for (int i = 0; i < 4; ++i)
            hv[i] = *(const float4*)&s_x[4 * ty + i][k4 * 4];
        #pragma unroll
        for (int kk = 0; kk < 4; ++kk) {
#if F32X2_OK
            const unsigned long long* wp =
                (const unsigned long long*)&s_w[k4 * 4 + kk][cb];
            unsigned long long w01 = wp[0];
            unsigned long long w23 = wp[1];
            #pragma unroll
            for (int i = 0; i < 4; ++i) {
                float hh = (kk == 0) ? hv[i].x : (kk == 1) ? hv[i].y
                         : (kk == 2) ? hv[i].z : hv[i].w;
                unsigned long long h2 = packdup(hh);
                fma2(acc2[i][0], h2, w01);
                fma2(acc2[i][1], h2, w23);
            }
#else
            float4 wv = *(const float4*)&s_w[k4 * 4 + kk][cb];
            #pragma unroll
            for (int i = 0; i < 4; ++i) {
                float hh = (kk == 0) ? hv[i].x : (kk == 1) ? hv[i].y
                         : (kk == 2) ? hv[i].z : hv[i].w;
                acc[i][0] = fmaf(hh, wv.x, acc[i][0]);
                acc[i][1] = fmaf(hh, wv.y, acc[i][1]);
                acc[i][2] = fmaf(hh, wv.z, acc[i][2]);
                acc[i][3] = fmaf(hh, wv.w, acc[i][3]);
            }
#endif
        }
    }

    int j = j0 + cb;
    float4 bv = *(const float4*)&g_bias[j];
    #pragma unroll
    for (int i = 0; i < 4; ++i) {
        int r = r0 + 4 * ty + i;
        if (r >= a) continue;
        float4 v;
#if F32X2_OK
        unpack2(acc2[i][0], v.x, v.y);
        unpack2(acc2[i][1], v.z, v.w);
#else
        v = make_float4(acc[i][0], acc[i][1], acc[i][2], acc[i][3]);
#endif
        v.x += bv.x; v.y += bv.y; v.z += bv.z; v.w += bv.w;
        *(float4*)&g_proj[r][t][j] = v;
    }
}

// ---------------- step kernel: pure recurrence slice ----------------
// stage h_{t-1} = tanh(proj[t-1] + sum of 4 partials), GEMM K-slice of W_hh -> partials(t).
// t == TT: finalize-only. grid (4 cg, 16 rg, 4 z) = 256 CTAs, 256 thr, 72KB smem -> 2 CTAs/SM.
__global__ __launch_bounds__(256, 2) void step_kernel(const float* __restrict__ h0, int t) {
    int a_prev = (t == 0) ? BB : g_active[t - 1];
    int r0 = blockIdx.y * RT;
    if (r0 >= a_prev) return;
    int z  = blockIdx.z;
    int cg = blockIdx.x;
    int j0 = cg * JT;
    int tid = threadIdx.x;
    int pbR = (t & 1) ^ 1, pbW = t & 1;

    __shared__ int s_b[RT];
    if (tid < RT) s_b[tid] = g_perm[r0 + tid];

    const int KS4 = KS / 4;   // 32

    // ---- finalize-only pass (t == TT): hout[TT-1] ----
    if (t == TT) {
        __syncthreads();
        if (cg != 0) return;
        for (int i4 = tid; i4 < RT * KS4; i4 += 256) {
            int rl = i4 / KS4;
            int kl = (i4 % KS4) * 4;
            int r  = r0 + rl;
            int kg = z * KS + kl;
            if (r >= a_prev) continue;
            float4 v = *(const float4*)&g_proj[r][TT - 1][kg];
            #pragma unroll
            for (int zp = 0; zp < NS; ++zp) {
                float4 p = *(const float4*)&g_part[pbR][zp][r][kg];
                v.x += p.x; v.y += p.y; v.z += p.z; v.w += p.w;
            }
            v.x = tanhf(v.x); v.y = tanhf(v.y); v.z = tanhf(v.z); v.w = tanhf(v.w);
            *(float4*)&g_hout[((size_t)s_b[rl] * TT + (TT - 1)) * HH + kg] = v;
        }
        return;
    }

    extern __shared__ char smem_raw[];
    float (*s_h)[KS] = (float (*)[KS])smem_raw;                  // 16 x 128 = 8 KB
    float (*s_w)[JT] = (float (*)[JT])(smem_raw + RT * KS * 4);  // 128 x 128 = 64 KB

    // whole W_hh slice via cp.async (4096 float4, 16/thread)
    {
        const float* gw = g_W + (size_t)(z * KS) * HH + j0;
        #pragma unroll
        for (int q = 0; q < 16; ++q) {
            int p  = tid + q * 256;
            int kk = p >> 5;
            int jj = (p & 31) * 4;
            cpa16(&s_w[kk][jj], gw + (size_t)kk * HH + jj);
        }
        CPA_COMMIT();
    }
    __syncthreads();   // s_b visible

    // ---- stage s_h (512 float4, 2/thread) ----
    #pragma unroll
    for (int q = 0; q < 2; ++q) {
        int i4 = tid + q * 256;
        int rl = i4 / KS4;
        int kl = (i4 % KS4) * 4;
        int r  = r0 + rl;
        int kg = z * KS + kl;
        float4 v;
        if (r >= a_prev) {
            v.x = v.y = v.z = v.w = 0.f;
        } else if (t == 0) {
            v = *(const float4*)&h0[(size_t)s_b[rl] * HH + kg];
        } else {
            v = *(const float4*)&g_proj[r][t - 1][kg];
            #pragma unroll
            for (int zp = 0; zp < NS; ++zp) {
                float4 p = *(const float4*)&g_part[pbR][zp][r][kg];
                v.x += p.x; v.y += p.y; v.z += p.z; v.w += p.w;
            }
            v.x = tanhf(v.x); v.y = tanhf(v.y); v.z = tanhf(v.z); v.w = tanhf(v.w);
            if (cg == 0)
                *(float4*)&g_hout[((size_t)s_b[rl] * TT + (t - 1)) * HH + kg] = v;
        }
        *(float4*)&s_h[rl][kl] = v;
    }

    CPA_WAIT0();
    __syncthreads();   // s_h + s_w ready

    // ---- GEMM: 16x128 tile, per-thread 2 rows x 4 cols, K = 128 ----
    int ty = tid >> 5;          // 0..7 (row group of 2)
    int tx = tid & 31;          // 0..31 (col group of 4)
    int cb = tx * 4;

#if F32X2_OK
    unsigned long long acc2[2][2];
    acc2[0][0] = acc2[0][1] = acc2[1][0] = acc2[1][1] = 0ull;
#else
    float acc[2][4];
    #pragma unroll
    for (int i = 0; i < 2; ++i)
        #pragma unroll
        for (int jj = 0; jj < 4; ++jj) acc[i][jj] = 0.f;
#endif

    #pragma unroll 8
    for (int k4 = 0; k4 < KS4; ++k4) {
        float4 hv[2];
        hv[0] = *(const float4*)&s_h[2 * ty][k4 * 4];
        hv[1] = *(const float4*)&s_h[2 * ty + 1][k4 * 4];
        #pragma unroll
        for (int kk = 0; kk < 4; ++kk) {
#if F32X2_OK
            const unsigned long long* wp =
                (const unsigned long long*)&s_w[k4 * 4 + kk][cb];
            unsigned long long w01 = wp[0];
            unsigned long long w23 = wp[1];
            #pragma unroll
            for (int i = 0; i < 2; ++i) {
                float hh = (kk == 0) ? hv[i].x : (kk == 1) ? hv[i].y
                         : (kk == 2) ? hv[i].z : hv[i].w;
                unsigned long long h2 = packdup(hh);
                fma2(acc2[i][0], h2, w01);
                fma2(acc2[i][1], h2, w23);
            }
#else
            float4 wv = *(const float4*)&s_w[k4 * 4 + kk][cb];
            #pragma unroll
            for (int i = 0; i < 2; ++i) {
                float hh = (kk == 0) ? hv[i].x : (kk == 1) ? hv[i].y
                         : (kk == 2) ? hv[i].z : hv[i].w;
                acc[i][0] = fmaf(hh, wv.x, acc[i][0]);
                acc[i][1] = fmaf(hh, wv.y, acc[i][1]);
                acc[i][2] = fmaf(hh, wv.z, acc[i][2]);
                acc[i][3] = fmaf(hh, wv.w, acc[i][3]);
            }
#endif
        }
    }

    // ---- epilogue: write slice partials (no bias; bias lives in proj) ----
    int j = j0 + cb;
    #pragma unroll
    for (int i = 0; i < 2; ++i) {
        int r = r0 + 2 * ty + i;
        float4 v;
#if F32X2_OK
        unpack2(acc2[i][0], v.x, v.y);
        unpack2(acc2[i][1], v.z, v.w);
#else
        v = make_float4(acc[i][0], acc[i][1], acc[i][2], acc[i][3]);
#endif
        *(float4*)&g_part[pbW][z][r][j] = v;
    }
}

// ---------------- FC head ----------------
__global__ __launch_bounds__(256) void fc_kernel(const int* __restrict__ lengths,
                                                 const float* __restrict__ W_fc,
                                                 const float* __restrict__ b_fc,
                                                 float* __restrict__ out,
                                                 int write_len_tail) {
    __shared__ float s_w[AA][HH];
    __shared__ float s_bias[AA];
    int tid = threadIdx.x;
    for (int i = tid; i < AA * HH; i += 256) s_w[i / HH][i % HH] = W_fc[i];
    if (tid < AA) s_bias[tid] = b_fc[tid];
    __syncthreads();

    int lane = tid & 31, wid = tid >> 5;
    int gw = blockIdx.x * 8 + wid;
    int nw = gridDim.x * 8;
    float myb = s_bias[lane < AA ? lane : 0];

    for (int item = gw; item < BB * TT; item += nw) {
        int b = item / TT, t = item % TT;
        int len = __ldg(&lengths[b]);
        float res;
        if (t < len) {
            const float4* hp = (const float4*)&g_hout[(size_t)item * HH];
            float4 h[4];
            #pragma unroll
            for (int q = 0; q < 4; ++q) h[q] = hp[q * 32 + lane];
            float myval = 0.f;
            #pragma unroll
            for (int a = 0; a < AA; ++a) {
                const float4* wp = (const float4*)&s_w[a][0];
                float p = 0.f;
                #pragma unroll
                for (int q = 0; q < 4; ++q) {
                    float4 w = wp[q * 32 + lane];
                    p = fmaf(h[q].x, w.x, p); p = fmaf(h[q].y, w.y, p);
                    p = fmaf(h[q].z, w.z, p); p = fmaf(h[q].w, w.w, p);
                }
                p += __shfl_xor_sync(0xFFFFFFFFu, p, 16);
                p += __shfl_xor_sync(0xFFFFFFFFu, p, 8);
                p += __shfl_xor_sync(0xFFFFFFFFu, p, 4);
                p += __shfl_xor_sync(0xFFFFFFFFu, p, 2);
                p += __shfl_xor_sync(0xFFFFFFFFu, p, 1);
                if (lane == a) myval = p;
            }
            res = myval + myb;
        } else {
            res = myb;
        }
        if (lane < AA) out[(size_t)item * AA + lane] = res;
    }

    if (write_len_tail && blockIdx.x == 0 && tid < BB) {
        out[(size_t)BB * TT * AA + tid] = (float)__ldg(&lengths[tid]);
    }
}

// ---------------- launch ----------------
extern "C" void kernel_launch(void* const* d_in, const int* in_sizes, int n_in,
                              void* d_out, int out_size) {
    const float* x      = (const float*)d_in[0];
    const float* h0     = (const float*)d_in[1];
    const int*   lengths= (const int*)  d_in[2];
    const float* W_ih   = (const float*)d_in[3];
    const float* W_hh   = (const float*)d_in[4];
    const float* b_ih   = (const float*)d_in[5];
    const float* b_hh   = (const float*)d_in[6];
    const float* W_fc   = (const float*)d_in[7];
    const float* b_fc   = (const float*)d_in[8];
    float* out = (float*)d_out;

    const int smem_step = RT * KS * 4 + KS * JT * 4;     // 8KB + 64KB = 73728
    const int smem_proj = 64 * II * 4 + II * JT * 4;     // 64KB + 128KB = 196608
    cudaFuncSetAttribute(step_kernel, cudaFuncAttributeMaxDynamicSharedMemorySize, smem_step);
    cudaFuncSetAttribute(proj_kernel, cudaFuncAttributeMaxDynamicSharedMemorySize, smem_proj);

    prep_sort<<<1, 512>>>(lengths);
    prep_pack<<<512, 256>>>(W_ih, W_hh, b_ih, b_hh);

    proj_kernel<<<dim3(HH / JT, BB / 64, TT), 512, smem_proj>>>(x);

    dim3 grid(HH / JT, BB / RT, NS);   // (4, 16, 4) = 256 CTAs
    for (int t = 0; t <= TT; ++t) {
        step_kernel<<<grid, 256, smem_step>>>(h0, t);
    }

    int tail = (out_size >= BB * TT * AA + BB) ? 1 : 0;
    fc_kernel<<<512, 256>>>(lengths, W_fc, b_fc, out, tail);
}